// round 10
// baseline (speedup 1.0000x reference)
#include <cuda_runtime.h>
#include <cuda_fp16.h>
#include <cuda_bf16.h>
#include <cstdint>
#include <cstddef>

// Problem shape (fixed by the dataset)
#define BB 4096   // batch rows
#define NN 8192   // memory slots
#define WW 64     // key width
#define NMT (BB / 128)        // 32 M-tiles
#define NTILES (NN / 128)     // 64 N-tiles

#define QSCALE 124.0f
#define QINV   (1.0f / 124.0f)

// ---------------------------------------------------------------------------
// Scratch (device globals — no allocations allowed)
// ---------------------------------------------------------------------------
__device__ __nv_bfloat16 g_kb[(size_t)BB * WW];  // bf16(k * escale), SW128-preswizzled
__device__ __nv_bfloat16 g_mb[(size_t)NN * WW];  // bf16(mem * mscale), SW128-preswizzled
__device__ char          g_q[(size_t)BB * NN];   // int8 quantized beta*sim (32 MB)
__device__ int           g_ready[NMT];           // per-mtile completion counters

#define SW128(x) ((x) ^ (((x) >> 3) & 0x70))

__device__ __forceinline__ uint32_t smem_u32(const void* p) {
    uint32_t a;
    asm("{ .reg .u64 t; cvta.to.shared.u64 t, %1; cvt.u32.u64 %0, t; }"
        : "=r"(a) : "l"(p));
    return a;
}

__device__ __forceinline__ int q8(float x) {
    return __float2int_rn(fminf(fmaxf(x * QSCALE, -127.0f), 127.0f));
}

// ---------------------------------------------------------------------------
// Kernel 1: per-row scale factors folded into bf16 operands (pre-swizzled).
// Also resets the readiness counters (replay-safe: runs before the fused
// kernel on the same stream every call).
// ---------------------------------------------------------------------------
__global__ void prep_kernel(const float* __restrict__ K,
                            const float* __restrict__ beta,
                            const float* __restrict__ M)
{
    if (blockIdx.x == 0 && threadIdx.x < NMT) g_ready[threadIdx.x] = 0;

    int w    = (blockIdx.x * blockDim.x + threadIdx.x) >> 5;
    int lane = threadIdx.x & 31;
    if (w >= BB + NN) return;

    bool is_k = (w < BB);
    int  row  = is_k ? w : (w - BB);
    const float* src = (is_k ? K : M) + (size_t)row * WW;

    float x0 = src[2 * lane];
    float x1 = src[2 * lane + 1];
    float ss = x0 * x0 + x1 * x1;
    #pragma unroll
    for (int o = 16; o; o >>= 1) ss += __shfl_xor_sync(0xFFFFFFFFu, ss, o);

    float nrm = sqrtf(ss);
    float sc;
    if (is_k) {
        float a  = 1.0f / fmaxf(nrm, 1e-12f);
        float n2 = nrm * a;                    // ||k_n||
        float b2 = 1.0f / fmaxf(n2, 1e-8f);
        sc = beta[row] * a * b2;
    } else {
        sc = 1.0f / fmaxf(nrm, 1e-8f);
    }

    uint32_t off = (uint32_t)(row & 7) * 128 + 4 * lane;
    uint32_t sw  = SW128(off);
    char* base = (char*)(is_k ? g_kb : g_mb) + (size_t)(row & ~7) * 128;
    __nv_bfloat162 v = __floats2bfloat162_rn(x0 * sc, x1 * sc);
    *(__nv_bfloat162*)(base + sw) = v;
}

// ---------------------------------------------------------------------------
// Fused producer-consumer kernel.
//   G role: bf16 mma.sync GEMM tile (128x128), int8 epilogue -> g_q, then
//           threadfence + atomicAdd(g_ready[mtile]).
//   F role: spins until its mtile's 64 G blocks are done, then per-row
//           softmax-gate-shift-pow-renormalize.
// Block order: [G(0) x64][F(0) x128, G(1) x64][F(1) x128, G(2) x64] ...
// Every F's producers precede it in dispatch order -> deadlock-free.
// ---------------------------------------------------------------------------
#define ESTRIDE 144   // bytes per staged row (16B-aligned; 36 words, mod32=4)

union __align__(1024) FusedSmem {
    struct {
        __nv_bfloat16 A[128 * 64];   // 16 KB
        __nv_bfloat16 B[128 * 64];   // 16 KB
    } in;
    char  e[128 * ESTRIDE];          // 18 KB int8 staging
    float fin[NN + 64];              // 33 KB finish row + reduction scratch
};

__device__ __forceinline__ uint32_t tile_addr(uint32_t base, int row, int kbyte) {
    return base + (uint32_t)(row & ~7) * 128 + SW128((uint32_t)(row & 7) * 128 + kbyte);
}

__device__ __forceinline__ float block_reduce_sum(float v, float* red)
{
    int tid = threadIdx.x;
    #pragma unroll
    for (int o = 16; o; o >>= 1) v += __shfl_xor_sync(0xFFFFFFFFu, v, o);
    if ((tid & 31) == 0) red[tid >> 5] = v;
    __syncthreads();
    if (tid < 32) {
        float x = (tid < 8) ? red[tid] : 0.0f;
        #pragma unroll
        for (int o = 4; o; o >>= 1) x += __shfl_xor_sync(0xFFFFFFFFu, x, o);
        if (tid == 0) red[16] = x;
    }
    __syncthreads();
    return red[16];
}

__device__ void gemm_role(FusedSmem& smem, int mtile, int ntile)
{
    int tid  = threadIdx.x;
    int wid  = tid >> 5;
    int lane = tid & 31;
    int n0   = ntile << 7;
    int m0   = mtile << 7;

    const uint4* gA = (const uint4*)((const char*)g_kb + (size_t)m0 * 128);
    const uint4* gB = (const uint4*)((const char*)g_mb + (size_t)n0 * 128);
    uint4* sA = (uint4*)smem.in.A;
    uint4* sB = (uint4*)smem.in.B;
    #pragma unroll
    for (int i = 0; i < 4; i++) {
        int idx = tid + 256 * i;
        sA[idx] = gA[idx];
        sB[idx] = gB[idx];
    }
    __syncthreads();

    uint32_t baseA = smem_u32(smem.in.A);
    uint32_t baseB = smem_u32(smem.in.B);

    int warp_m = wid >> 2;
    int warp_n = wid & 3;
    int m_base = warp_m * 64;
    int n_base = warp_n * 32;

    float acc[4][4][4];
    #pragma unroll
    for (int a = 0; a < 4; a++)
        #pragma unroll
        for (int b = 0; b < 4; b++)
            #pragma unroll
            for (int c = 0; c < 4; c++) acc[a][b][c] = 0.0f;

    #pragma unroll
    for (int ks = 0; ks < 4; ks++) {
        int k0 = ks * 16;

        uint32_t a[4][4];
        #pragma unroll
        for (int mg = 0; mg < 4; mg++) {
            int r  = m_base + mg * 16 + (lane & 15);
            int kb = (k0 + ((lane >> 4) << 3)) * 2;
            uint32_t addr = tile_addr(baseA, r, kb);
            asm volatile("ldmatrix.sync.aligned.m8n8.x4.shared.b16 {%0,%1,%2,%3}, [%4];"
                         : "=r"(a[mg][0]), "=r"(a[mg][1]), "=r"(a[mg][2]), "=r"(a[mg][3])
                         : "r"(addr));
        }
        uint32_t b[2][4];
        #pragma unroll
        for (int ngp = 0; ngp < 2; ngp++) {
            int n  = n_base + ngp * 16 + (lane & 7) + ((lane >> 4) << 3);
            int kb = (k0 + (((lane >> 3) & 1) << 3)) * 2;
            uint32_t addr = tile_addr(baseB, n, kb);
            asm volatile("ldmatrix.sync.aligned.m8n8.x4.shared.b16 {%0,%1,%2,%3}, [%4];"
                         : "=r"(b[ngp][0]), "=r"(b[ngp][1]), "=r"(b[ngp][2]), "=r"(b[ngp][3])
                         : "r"(addr));
        }
        #pragma unroll
        for (int mg = 0; mg < 4; mg++)
            #pragma unroll
            for (int ng = 0; ng < 4; ng++) {
                int ngp = ng >> 1, sel = (ng & 1) * 2;
                asm volatile(
                    "mma.sync.aligned.m16n8k16.row.col.f32.bf16.bf16.f32 "
                    "{%0,%1,%2,%3}, {%4,%5,%6,%7}, {%8,%9}, {%0,%1,%2,%3};"
                    : "+f"(acc[mg][ng][0]), "+f"(acc[mg][ng][1]),
                      "+f"(acc[mg][ng][2]), "+f"(acc[mg][ng][3])
                    : "r"(a[mg][0]), "r"(a[mg][1]), "r"(a[mg][2]), "r"(a[mg][3]),
                      "r"(b[ngp][sel]), "r"(b[ngp][sel + 1]));
            }
    }

    __syncthreads();   // ldmatrix reads done before the union is repurposed

    int groupr = lane >> 2;
    int cpair  = (lane & 3) << 1;
    #pragma unroll
    for (int mg = 0; mg < 4; mg++) {
        #pragma unroll
        for (int ng = 0; ng < 4; ng++) {
            int r = m_base + mg * 16 + groupr;
            int c = n_base + ng * 8 + cpair;
            int q0 = q8(acc[mg][ng][0]);
            int q1 = q8(acc[mg][ng][1]);
            int q2 = q8(acc[mg][ng][2]);
            int q3 = q8(acc[mg][ng][3]);
            *(short*)&smem.e[r * ESTRIDE + c] =
                (short)((q0 & 0xFF) | ((q1 & 0xFF) << 8));
            *(short*)&smem.e[(r + 8) * ESTRIDE + c] =
                (short)((q2 & 0xFF) | ((q3 & 0xFF) << 8));
        }
    }
    __syncthreads();

    #pragma unroll
    for (int i = 0; i < 4; i++) {
        int gi = tid + 256 * i;
        int r  = gi >> 3;
        int c  = gi & 7;
        uint4 v = *(const uint4*)&smem.e[r * ESTRIDE + c * 16];
        *(uint4*)(g_q + (size_t)(m0 + r) * NN + n0 + c * 16) = v;
    }

    // Publish: my stores -> my fence -> barrier -> tid0's release count.
    __threadfence();
    __syncthreads();
    if (tid == 0) atomicAdd(&g_ready[mtile], 1);
}

__device__ void finish_role(FusedSmem& smem, int b,
                            const float* __restrict__ prev,
                            const float* __restrict__ g,
                            const float* __restrict__ s,
                            const float* __restrict__ gamma,
                            float* __restrict__ out)
{
    float* buf = smem.fin;
    float* red = smem.fin + NN;
    int tid = threadIdx.x;
    int mt  = b >> 7;

    // Wait for this row's 64 producer tiles.
    if (tid == 0) {
        while (atomicAdd(&g_ready[mt], 0) < NTILES) __nanosleep(200);
    }
    __syncthreads();
    __threadfence();   // acquire: order subsequent loads after the flag read

    const uint4* q4 = (const uint4*)(g_q + (size_t)b * NN);
    float z = 0.0f;
    #pragma unroll
    for (int j = 0; j < 2; j++) {
        int i = tid + 256 * j;
        uint4 v = q4[i];
        float* dst = &buf[i * 16];
        uint32_t wds[4] = {v.x, v.y, v.z, v.w};
        #pragma unroll
        for (int w = 0; w < 4; w++) {
            uint32_t u = wds[w];
            float e0 = __expf((float)(int)(char)(u)        * QINV);
            float e1 = __expf((float)(int)(char)(u >> 8)   * QINV);
            float e2 = __expf((float)(int)(char)(u >> 16)  * QINV);
            float e3 = __expf((float)(int)(char)(u >> 24)  * QINV);
            dst[4 * w + 0] = e0;
            dst[4 * w + 1] = e1;
            dst[4 * w + 2] = e2;
            dst[4 * w + 3] = e3;
            z += (e0 + e1) + (e2 + e3);
        }
    }
    float Z = block_reduce_sum(z, red);

    float gb = g[b];
    float gm = gamma[b];
    float s0 = s[3 * b], s1 = s[3 * b + 1], s2 = s[3 * b + 2];
    float mx  = fmaxf(s0, fmaxf(s1, s2));
    float es0 = __expf(s0 - mx), es1 = __expf(s1 - mx), es2 = __expf(s2 - mx);
    float inv3 = 1.0f / (es0 + es1 + es2);
    float ss0 = es0 * inv3, ss1 = es1 * inv3, ss2 = es2 * inv3;

    float gcw = gb / Z;
    float om  = 1.0f - gb;

    const float4* p4 = (const float4*)(prev + (size_t)b * NN);
    #pragma unroll
    for (int j = 0; j < 8; j++) {
        int i = tid + 256 * j;
        float4 v = *(float4*)&buf[4 * i];
        float4 p = p4[i];
        v.x = gcw * v.x + om * p.x;
        v.y = gcw * v.y + om * p.y;
        v.z = gcw * v.z + om * p.z;
        v.w = gcw * v.w + om * p.w;
        *(float4*)&buf[4 * i] = v;
    }
    __syncthreads();

    float r[32];
    float ssum = 0.0f;
    #pragma unroll
    for (int j = 0; j < 32; j++) {
        int i = tid + 256 * j;
        float left  = (i > 0)      ? buf[i - 1] : 0.0f;
        float mid   = buf[i];
        float right = (i < NN - 1) ? buf[i + 1] : 0.0f;
        float sh = ss0 * left + ss1 * mid + ss2 * right;
        float sp = __powf(sh, gm);
        r[j] = sp;
        ssum += sp;
    }
    float S  = block_reduce_sum(ssum, red);
    float sc = 1.0f / (S + 1e-8f);

    float* orow = out + (size_t)b * NN;
    #pragma unroll
    for (int j = 0; j < 32; j++)
        orow[tid + 256 * j] = r[j] * sc;
}

// Grid = 64 + 31*192 + 128 = 6144 blocks.
// bid < 64                     -> G(mtile 0, ntile bid)
// else idx = bid-64, gq = idx/192, r = idx%192:
//   r < 128 -> F(row = gq*128 + r)
//   else    -> G(mtile gq+1, ntile r-128)
__global__ __launch_bounds__(256) void fused_kernel(
    const float* __restrict__ prev,
    const float* __restrict__ g,
    const float* __restrict__ s,
    const float* __restrict__ gamma,
    float* __restrict__ out)
{
    __shared__ FusedSmem smem;
    int bid = blockIdx.x;

    if (bid < NTILES) {
        gemm_role(smem, 0, bid);
    } else {
        int idx = bid - NTILES;
        int gq  = idx / 192;
        int r   = idx % 192;
        if (r < 128) finish_role(smem, gq * 128 + r, prev, g, s, gamma, out);
        else         gemm_role(smem, gq + 1, r - 128);
    }
}

// ---------------------------------------------------------------------------
// Launch. Inputs (metadata order): k, beta, g, s, gamma, prev_weights, memory
// ---------------------------------------------------------------------------
extern "C" void kernel_launch(void* const* d_in, const int* in_sizes, int n_in,
                              void* d_out, int out_size)
{
    const float* K    = (const float*)d_in[0];
    const float* beta = (const float*)d_in[1];
    const float* g    = (const float*)d_in[2];
    const float* s    = (const float*)d_in[3];
    const float* gam  = (const float*)d_in[4];
    const float* prev = (const float*)d_in[5];
    const float* M    = (const float*)d_in[6];
    float* out = (float*)d_out;

    prep_kernel<<<(BB + NN) / 8, 256>>>(K, beta, M);
    fused_kernel<<<NTILES + (NMT - 1) * 192 + 128, 256>>>(prev, g, s, gam, out);
}

// round 11
// speedup vs baseline: 1.7928x; 1.7928x over previous
#include <cuda_runtime.h>
#include <cuda_fp16.h>
#include <cuda_bf16.h>
#include <cstdint>
#include <cstddef>

// Problem shape (fixed by the dataset)
#define BB 4096   // batch rows
#define NN 8192   // memory slots
#define WW 64     // key width

#define QSCALE 124.0f
#define QINV   (1.0f / 124.0f)

// ---------------------------------------------------------------------------
// Scratch (device globals — no allocations allowed)
// ---------------------------------------------------------------------------
__device__ __nv_bfloat16 g_kb[(size_t)BB * WW];  // bf16(k * escale), SW128-preswizzled
__device__ __nv_bfloat16 g_mb[(size_t)NN * WW];  // bf16(mem * mscale), SW128-preswizzled
__device__ char          g_q[(size_t)BB * NN];   // int8 quantized beta*sim (32 MB)

#define SW128(x) ((x) ^ (((x) >> 3) & 0x70))

__device__ __forceinline__ uint32_t smem_u32(const void* p) {
    uint32_t a;
    asm("{ .reg .u64 t; cvta.to.shared.u64 t, %1; cvt.u32.u64 %0, t; }"
        : "=r"(a) : "l"(p));
    return a;
}

__device__ __forceinline__ int q8(float x) {
    return __float2int_rn(fminf(fmaxf(x * QSCALE, -127.0f), 127.0f));
}

// ---------------------------------------------------------------------------
// Kernel 1: per-row scale factors folded into bf16 operands (pre-swizzled).
// ---------------------------------------------------------------------------
__global__ void prep_kernel(const float* __restrict__ K,
                            const float* __restrict__ beta,
                            const float* __restrict__ M)
{
    int w    = (blockIdx.x * blockDim.x + threadIdx.x) >> 5;
    int lane = threadIdx.x & 31;
    if (w >= BB + NN) return;

    bool is_k = (w < BB);
    int  row  = is_k ? w : (w - BB);
    const float* src = (is_k ? K : M) + (size_t)row * WW;

    float x0 = src[2 * lane];
    float x1 = src[2 * lane + 1];
    float ss = x0 * x0 + x1 * x1;
    #pragma unroll
    for (int o = 16; o; o >>= 1) ss += __shfl_xor_sync(0xFFFFFFFFu, ss, o);

    float nrm = sqrtf(ss);
    float sc;
    if (is_k) {
        float a  = 1.0f / fmaxf(nrm, 1e-12f);
        float n2 = nrm * a;                    // ||k_n||
        float b2 = 1.0f / fmaxf(n2, 1e-8f);
        sc = beta[row] * a * b2;
    } else {
        sc = 1.0f / fmaxf(nrm, 1e-8f);
    }

    uint32_t off = (uint32_t)(row & 7) * 128 + 4 * lane;
    uint32_t sw  = SW128(off);
    char* base = (char*)(is_k ? g_kb : g_mb) + (size_t)(row & ~7) * 128;
    __nv_bfloat162 v = __floats2bfloat162_rn(x0 * sc, x1 * sc);
    *(__nv_bfloat162*)(base + sw) = v;
}

// ---------------------------------------------------------------------------
// Kernel 2: bf16 tensor-core GEMM (mma.sync m16n8k16), int8 epilogue.
//   CTA tile 64x128 (M x N), K=64. 8 warps in 2(M)x4(N); warp tile 32x32.
//   ~60 regs/thread -> 4 CTAs/SM -> 8 warps/SMSP for latency hiding
//   (the round-9 profile showed 84% exposed-latency at 4 warps/SMSP).
//   Operands arrive SW128-preswizzled -> straight G->S copies; ldmatrix
//   recomputes the same swizzle (conflict-free).
//   Epilogue: quantize to int8 via SMEM staging (stride 144B), coalesced
//   uint4 flush.
// ---------------------------------------------------------------------------
#define ESTRIDE 144   // bytes per staged row (16B-aligned; 36 words, mod32=4)

union __align__(1024) GemmSmem {
    struct {
        __nv_bfloat16 A[64 * 64];    // 8 KB
        __nv_bfloat16 B[128 * 64];   // 16 KB
    } in;
    char e[64 * ESTRIDE];            // 9 KB staging for the int8 tile
};

__device__ __forceinline__ uint32_t tile_addr(uint32_t base, int row, int kbyte) {
    return base + (uint32_t)(row & ~7) * 128 + SW128((uint32_t)(row & 7) * 128 + kbyte);
}

__global__ __launch_bounds__(256, 4) void gemm_q_kernel()
{
    __shared__ GemmSmem smem;
    int tid  = threadIdx.x;
    int wid  = tid >> 5;
    int lane = tid & 31;
    int n0   = blockIdx.x << 7;    // 128-wide N tile
    int m0   = blockIdx.y << 6;    // 64-tall M tile

    // Copy pre-swizzled tiles. A: 8KB = 512 uint4 (2/thread); B: 16KB (4/thread).
    const uint4* gA = (const uint4*)((const char*)g_kb + (size_t)m0 * 128);
    const uint4* gB = (const uint4*)((const char*)g_mb + (size_t)n0 * 128);
    uint4* sA = (uint4*)smem.in.A;
    uint4* sB = (uint4*)smem.in.B;
    #pragma unroll
    for (int i = 0; i < 2; i++) sA[tid + 256 * i] = gA[tid + 256 * i];
    #pragma unroll
    for (int i = 0; i < 4; i++) sB[tid + 256 * i] = gB[tid + 256 * i];
    __syncthreads();

    uint32_t baseA = smem_u32(smem.in.A);
    uint32_t baseB = smem_u32(smem.in.B);

    int warp_m = wid >> 2;           // 0..1 -> 32 rows each
    int warp_n = wid & 3;            // 0..3 -> 32 cols each
    int m_base = warp_m * 32;
    int n_base = warp_n * 32;

    float acc[2][4][4];              // [mg][ng][frag]
    #pragma unroll
    for (int a = 0; a < 2; a++)
        #pragma unroll
        for (int b = 0; b < 4; b++)
            #pragma unroll
            for (int c = 0; c < 4; c++) acc[a][b][c] = 0.0f;

    #pragma unroll
    for (int ks = 0; ks < 4; ks++) {     // K = 4 x 16
        int k0 = ks * 16;

        // A fragments: 2 x ldmatrix.x4 (m16 x k16 each)
        uint32_t a[2][4];
        #pragma unroll
        for (int mg = 0; mg < 2; mg++) {
            int r  = m_base + mg * 16 + (lane & 15);
            int kb = (k0 + ((lane >> 4) << 3)) * 2;
            uint32_t addr = tile_addr(baseA, r, kb);
            asm volatile("ldmatrix.sync.aligned.m8n8.x4.shared.b16 {%0,%1,%2,%3}, [%4];"
                         : "=r"(a[mg][0]), "=r"(a[mg][1]), "=r"(a[mg][2]), "=r"(a[mg][3])
                         : "r"(addr));
        }
        // B fragments: 2 x ldmatrix.x4, each covers two n8 groups x k16.
        uint32_t b[2][4];
        #pragma unroll
        for (int ngp = 0; ngp < 2; ngp++) {
            int n  = n_base + ngp * 16 + (lane & 7) + ((lane >> 4) << 3);
            int kb = (k0 + (((lane >> 3) & 1) << 3)) * 2;
            uint32_t addr = tile_addr(baseB, n, kb);
            asm volatile("ldmatrix.sync.aligned.m8n8.x4.shared.b16 {%0,%1,%2,%3}, [%4];"
                         : "=r"(b[ngp][0]), "=r"(b[ngp][1]), "=r"(b[ngp][2]), "=r"(b[ngp][3])
                         : "r"(addr));
        }
        // 8 MMAs
        #pragma unroll
        for (int mg = 0; mg < 2; mg++)
            #pragma unroll
            for (int ng = 0; ng < 4; ng++) {
                int ngp = ng >> 1, sel = (ng & 1) * 2;
                asm volatile(
                    "mma.sync.aligned.m16n8k16.row.col.f32.bf16.bf16.f32 "
                    "{%0,%1,%2,%3}, {%4,%5,%6,%7}, {%8,%9}, {%0,%1,%2,%3};"
                    : "+f"(acc[mg][ng][0]), "+f"(acc[mg][ng][1]),
                      "+f"(acc[mg][ng][2]), "+f"(acc[mg][ng][3])
                    : "r"(a[mg][0]), "r"(a[mg][1]), "r"(a[mg][2]), "r"(a[mg][3]),
                      "r"(b[ngp][sel]), "r"(b[ngp][sel + 1]));
            }
    }

    __syncthreads();   // ldmatrix reads done before the union is repurposed

    // Stage quantized int8 tile (64 rows x 128 cols).
    int groupr = lane >> 2;
    int cpair  = (lane & 3) << 1;
    #pragma unroll
    for (int mg = 0; mg < 2; mg++) {
        #pragma unroll
        for (int ng = 0; ng < 4; ng++) {
            int r = m_base + mg * 16 + groupr;
            int c = n_base + ng * 8 + cpair;
            int q0 = q8(acc[mg][ng][0]);
            int q1 = q8(acc[mg][ng][1]);
            int q2 = q8(acc[mg][ng][2]);
            int q3 = q8(acc[mg][ng][3]);
            *(short*)&smem.e[r * ESTRIDE + c] =
                (short)((q0 & 0xFF) | ((q1 & 0xFF) << 8));
            *(short*)&smem.e[(r + 8) * ESTRIDE + c] =
                (short)((q2 & 0xFF) | ((q3 & 0xFF) << 8));
        }
    }
    __syncthreads();

    // Coalesced flush: 64 rows x 128B = 512 uint4 = 256 threads x 2.
    #pragma unroll
    for (int i = 0; i < 2; i++) {
        int gi = tid + 256 * i;
        int r  = gi >> 3;
        int c  = gi & 7;
        uint4 v = *(const uint4*)&smem.e[r * ESTRIDE + c * 16];
        *(uint4*)(g_q + (size_t)(m0 + r) * NN + n0 + c * 16) = v;
    }
}

// ---------------------------------------------------------------------------
// Kernel 3: per-row finish. One CTA (256 threads) per batch row.
//   Dequant int8 -> e = exp(q/QSCALE); Z summed from the SAME quantized
//   values the weights use (renormalization cancels most quant error).
//   Then gate with prev, 3-tap shift, pow, renormalize.
// ---------------------------------------------------------------------------
#define FIN_SMEM ((NN + 64) * 4)   // 33 KB

__device__ __forceinline__ float block_reduce_sum(float v, float* red)
{
    int tid = threadIdx.x;
    #pragma unroll
    for (int o = 16; o; o >>= 1) v += __shfl_xor_sync(0xFFFFFFFFu, v, o);
    if ((tid & 31) == 0) red[tid >> 5] = v;
    __syncthreads();
    if (tid < 32) {
        float x = (tid < 8) ? red[tid] : 0.0f;
        #pragma unroll
        for (int o = 4; o; o >>= 1) x += __shfl_xor_sync(0xFFFFFFFFu, x, o);
        if (tid == 0) red[16] = x;
    }
    __syncthreads();
    return red[16];
}

__global__ __launch_bounds__(256) void finish_kernel(
    const float* __restrict__ prev,
    const float* __restrict__ g,
    const float* __restrict__ s,
    const float* __restrict__ gamma,
    float* __restrict__ out)
{
    extern __shared__ float sm[];
    float* buf = sm;
    float* red = sm + NN;

    int b   = blockIdx.x;
    int tid = threadIdx.x;

    const uint4* q4 = (const uint4*)(g_q + (size_t)b * NN);
    float z = 0.0f;
    #pragma unroll
    for (int j = 0; j < 2; j++) {
        int i = tid + 256 * j;
        uint4 v = q4[i];
        float* dst = &buf[i * 16];
        uint32_t wds[4] = {v.x, v.y, v.z, v.w};
        #pragma unroll
        for (int w = 0; w < 4; w++) {
            uint32_t u = wds[w];
            float e0 = __expf((float)(int)(char)(u)        * QINV);
            float e1 = __expf((float)(int)(char)(u >> 8)   * QINV);
            float e2 = __expf((float)(int)(char)(u >> 16)  * QINV);
            float e3 = __expf((float)(int)(char)(u >> 24)  * QINV);
            dst[4 * w + 0] = e0;
            dst[4 * w + 1] = e1;
            dst[4 * w + 2] = e2;
            dst[4 * w + 3] = e3;
            z += (e0 + e1) + (e2 + e3);
        }
    }
    float Z = block_reduce_sum(z, red);

    float gb = g[b];
    float gm = gamma[b];
    float s0 = s[3 * b], s1 = s[3 * b + 1], s2 = s[3 * b + 2];
    float mx  = fmaxf(s0, fmaxf(s1, s2));
    float es0 = __expf(s0 - mx), es1 = __expf(s1 - mx), es2 = __expf(s2 - mx);
    float inv3 = 1.0f / (es0 + es1 + es2);
    float ss0 = es0 * inv3, ss1 = es1 * inv3, ss2 = es2 * inv3;

    float gcw = gb / Z;
    float om  = 1.0f - gb;

    const float4* p4 = (const float4*)(prev + (size_t)b * NN);
    #pragma unroll
    for (int j = 0; j < 8; j++) {
        int i = tid + 256 * j;
        float4 v = *(float4*)&buf[4 * i];
        float4 p = p4[i];
        v.x = gcw * v.x + om * p.x;
        v.y = gcw * v.y + om * p.y;
        v.z = gcw * v.z + om * p.z;
        v.w = gcw * v.w + om * p.w;
        *(float4*)&buf[4 * i] = v;
    }
    __syncthreads();

    float r[32];
    float ssum = 0.0f;
    #pragma unroll
    for (int j = 0; j < 32; j++) {
        int i = tid + 256 * j;
        float left  = (i > 0)      ? buf[i - 1] : 0.0f;
        float mid   = buf[i];
        float right = (i < NN - 1) ? buf[i + 1] : 0.0f;
        float sh = ss0 * left + ss1 * mid + ss2 * right;
        float sp = __powf(sh, gm);
        r[j] = sp;
        ssum += sp;
    }
    float S  = block_reduce_sum(ssum, red);
    float sc = 1.0f / (S + 1e-8f);

    float* orow = out + (size_t)b * NN;
    #pragma unroll
    for (int j = 0; j < 32; j++)
        orow[tid + 256 * j] = r[j] * sc;
}

// ---------------------------------------------------------------------------
// Launch. Inputs (metadata order): k, beta, g, s, gamma, prev_weights, memory
// Serial single-stream (both overlap schemes measured slower).
// ---------------------------------------------------------------------------
extern "C" void kernel_launch(void* const* d_in, const int* in_sizes, int n_in,
                              void* d_out, int out_size)
{
    const float* K    = (const float*)d_in[0];
    const float* beta = (const float*)d_in[1];
    const float* g    = (const float*)d_in[2];
    const float* s    = (const float*)d_in[3];
    const float* gam  = (const float*)d_in[4];
    const float* prev = (const float*)d_in[5];
    const float* M    = (const float*)d_in[6];
    float* out = (float*)d_out;

    prep_kernel<<<(BB + NN) / 8, 256>>>(K, beta, M);

    // 64 N-tiles x 64 M-tiles (CTA tile 64x128), 256 threads.
    gemm_q_kernel<<<dim3(NN / 128, BB / 64), 256>>>();

    finish_kernel<<<BB, 256, FIN_SMEM>>>(prev, g, s, gam, out);
}

// round 12
// speedup vs baseline: 1.8696x; 1.0428x over previous
#include <cuda_runtime.h>
#include <cuda_fp16.h>
#include <cuda_bf16.h>
#include <cstdint>
#include <cstddef>

// Problem shape (fixed by the dataset)
#define BB 4096   // batch rows
#define NN 8192   // memory slots
#define WW 64     // key width

#define QSCALE 124.0f
#define QINV   (1.0f / 124.0f)
// int8 input quantization: unit vectors scaled by 127; dot scale 1/127^2.
#define CBFAC  (QSCALE / 16129.0f)

// ---------------------------------------------------------------------------
// Scratch (device globals — no allocations allowed)
// ---------------------------------------------------------------------------
__device__ char  g_kb[(size_t)BB * WW];   // int8(k_c * 127), SW64-preswizzled, 64B rows
__device__ char  g_mb[(size_t)NN * WW];   // int8(m_c * 127), SW64-preswizzled
__device__ float g_cb[BB];                // beta[row] * QSCALE / 127^2
__device__ char  g_q[(size_t)BB * NN];    // int8 quantized beta*sim (32 MB)

// 64B-row swizzle: 16B unit index (bits[5:4]) ^= row>>1 (bits[8:7]).
// Verified: each 8-row ldmatrix phase hits all 32 banks exactly once.
#define SW64(x) ((x) ^ (((x) >> 3) & 0x30))

__device__ __forceinline__ uint32_t smem_u32(const void* p) {
    uint32_t a;
    asm("{ .reg .u64 t; cvta.to.shared.u64 t, %1; cvt.u32.u64 %0, t; }"
        : "=r"(a) : "l"(p));
    return a;
}

__device__ __forceinline__ int q8(float x) {
    return __float2int_rn(fminf(fmaxf(x, -127.0f), 127.0f));
}

// ---------------------------------------------------------------------------
// Kernel 1: normalize rows, quantize to int8 (scale 127), pre-swizzle.
//   k rows:  k_c = k/max(||k||,1e-12)/max(||k_n||,1e-8)  (unit);
//            also g_cb[row] = beta*QSCALE/127^2
//   mem rows: m_c = m/max(||m||,1e-8)                    (unit)
// One warp per row; lane handles cols (2*lane, 2*lane+1).
// ---------------------------------------------------------------------------
__global__ void prep_kernel(const float* __restrict__ K,
                            const float* __restrict__ beta,
                            const float* __restrict__ M)
{
    int w    = (blockIdx.x * blockDim.x + threadIdx.x) >> 5;
    int lane = threadIdx.x & 31;
    if (w >= BB + NN) return;

    bool is_k = (w < BB);
    int  row  = is_k ? w : (w - BB);
    const float* src = (is_k ? K : M) + (size_t)row * WW;

    float x0 = src[2 * lane];
    float x1 = src[2 * lane + 1];
    float ss = x0 * x0 + x1 * x1;
    #pragma unroll
    for (int o = 16; o; o >>= 1) ss += __shfl_xor_sync(0xFFFFFFFFu, ss, o);

    float nrm = sqrtf(ss);
    float sc;
    if (is_k) {
        float a  = 1.0f / fmaxf(nrm, 1e-12f);
        float n2 = nrm * a;                    // ||k_n||
        float b2 = 1.0f / fmaxf(n2, 1e-8f);
        sc = a * b2;                           // unit-vector scale (beta -> g_cb)
        if (lane == 0) g_cb[row] = beta[row] * CBFAC;
    } else {
        sc = 1.0f / fmaxf(nrm, 1e-8f);
    }

    int qa = q8(x0 * sc * 127.0f);
    int qb = q8(x1 * sc * 127.0f);

    // Pre-swizzled 2-byte store: row stride 64B; SW64 permutes 16B units
    // inside each 8-row (512B) block; a 2B store stays inside one 16B unit.
    uint32_t off = (uint32_t)(row & 7) * 64 + 2 * lane;
    uint32_t sw  = SW64(off);
    char* base = (is_k ? g_kb : g_mb) + (size_t)(row & ~7) * 64;
    *(short*)(base + sw) = (short)((qa & 0xFF) | ((qb & 0xFF) << 8));
}

// ---------------------------------------------------------------------------
// Kernel 2: int8 tensor-core GEMM (mma.sync m16n8k32.s8), int8 epilogue.
//   CTA tile 128x128, K=64 -> only 2 K-steps. 8 warps 2(M)x4(N), warp 64x32.
//   Per warp: 12 ldmatrix + 32 MMA (was 24 + 64 in bf16) — the round-11
//   experiment showed the GEMM is bound by per-warp serial work, so halving
//   the instruction stream is the lever.
//   s8-k32 fragments are byte-identical to b16-k16 fragments, so the proven
//   ldmatrix addressing carries over with byte (not x2) offsets.
//   Epilogue: d * (beta*124/127^2) -> int8, SMEM staging, coalesced flush.
// ---------------------------------------------------------------------------
#define ESTRIDE 144   // bytes per staged row (16B-aligned; 36 words, mod32=4)

union __align__(1024) GemmSmem {
    struct {
        char A[128 * 64];   // 8 KB (SW64 rows)
        char B[128 * 64];   // 8 KB
    } in;
    char e[128 * ESTRIDE];  // 18 KB staging for the int8 output tile
};

__device__ __forceinline__ uint32_t tile_addr(uint32_t base, int row, int kbyte) {
    return base + (uint32_t)(row & ~7) * 64 + SW64((uint32_t)(row & 7) * 64 + kbyte);
}

__global__ __launch_bounds__(256) void gemm_q_kernel()
{
    __shared__ GemmSmem smem;
    int tid  = threadIdx.x;
    int wid  = tid >> 5;
    int lane = tid & 31;
    int n0   = blockIdx.x << 7;
    int m0   = blockIdx.y << 7;

    // Copy pre-swizzled tiles: 8KB each = 512 uint4 = 256 threads x 2.
    const uint4* gA = (const uint4*)(g_kb + (size_t)m0 * 64);
    const uint4* gB = (const uint4*)(g_mb + (size_t)n0 * 64);
    uint4* sA = (uint4*)smem.in.A;
    uint4* sB = (uint4*)smem.in.B;
    #pragma unroll
    for (int i = 0; i < 2; i++) {
        int idx = tid + 256 * i;
        sA[idx] = gA[idx];
        sB[idx] = gB[idx];
    }
    __syncthreads();

    uint32_t baseA = smem_u32(smem.in.A);
    uint32_t baseB = smem_u32(smem.in.B);

    int warp_m = wid >> 2;           // 0..1 -> 64 rows
    int warp_n = wid & 3;            // 0..3 -> 32 cols
    int m_base = warp_m * 64;
    int n_base = warp_n * 32;

    int acc[4][4][4];                // [mg][ng][frag], s32
    #pragma unroll
    for (int a = 0; a < 4; a++)
        #pragma unroll
        for (int b = 0; b < 4; b++)
            #pragma unroll
            for (int c = 0; c < 4; c++) acc[a][b][c] = 0;

    #pragma unroll
    for (int ks = 0; ks < 2; ks++) {     // K = 2 x 32
        int k0 = ks * 32;

        // A fragments: 4 x ldmatrix.x4 (m16 x k32 each; b16 view).
        uint32_t a[4][4];
        #pragma unroll
        for (int mg = 0; mg < 4; mg++) {
            int r  = m_base + mg * 16 + (lane & 15);
            int kb = k0 + ((lane >> 4) << 4);
            uint32_t addr = tile_addr(baseA, r, kb);
            asm volatile("ldmatrix.sync.aligned.m8n8.x4.shared.b16 {%0,%1,%2,%3}, [%4];"
                         : "=r"(a[mg][0]), "=r"(a[mg][1]), "=r"(a[mg][2]), "=r"(a[mg][3])
                         : "r"(addr));
        }
        // B fragments: 2 x ldmatrix.x4, each covers two n8 groups x k32.
        // lanes 0-7: n+0..7 @klo | 8-15: same @khi | 16-23: n+8..15 @klo | 24-31: @khi
        uint32_t b[2][4];
        #pragma unroll
        for (int ngp = 0; ngp < 2; ngp++) {
            int n  = n_base + ngp * 16 + (lane & 7) + ((lane >> 4) << 3);
            int kb = k0 + (((lane >> 3) & 1) << 4);
            uint32_t addr = tile_addr(baseB, n, kb);
            asm volatile("ldmatrix.sync.aligned.m8n8.x4.shared.b16 {%0,%1,%2,%3}, [%4];"
                         : "=r"(b[ngp][0]), "=r"(b[ngp][1]), "=r"(b[ngp][2]), "=r"(b[ngp][3])
                         : "r"(addr));
        }
        // 16 MMAs per k-step
        #pragma unroll
        for (int mg = 0; mg < 4; mg++)
            #pragma unroll
            for (int ng = 0; ng < 4; ng++) {
                int ngp = ng >> 1, sel = (ng & 1) * 2;
                asm volatile(
                    "mma.sync.aligned.m16n8k32.row.col.s32.s8.s8.s32 "
                    "{%0,%1,%2,%3}, {%4,%5,%6,%7}, {%8,%9}, {%0,%1,%2,%3};"
                    : "+r"(acc[mg][ng][0]), "+r"(acc[mg][ng][1]),
                      "+r"(acc[mg][ng][2]), "+r"(acc[mg][ng][3])
                    : "r"(a[mg][0]), "r"(a[mg][1]), "r"(a[mg][2]), "r"(a[mg][3]),
                      "r"(b[ngp][sel]), "r"(b[ngp][sel + 1]));
            }
    }

    __syncthreads();   // ldmatrix reads done before the union is repurposed

    // Stage quantized int8 output tile. Fragment rows: groupr & groupr+8.
    int groupr = lane >> 2;
    int cpair  = (lane & 3) << 1;
    #pragma unroll
    for (int mg = 0; mg < 4; mg++) {
        int r_lo = m_base + mg * 16 + groupr;
        float cb_lo = g_cb[m0 + r_lo];
        float cb_hi = g_cb[m0 + r_lo + 8];
        #pragma unroll
        for (int ng = 0; ng < 4; ng++) {
            int c = n_base + ng * 8 + cpair;
            int q0 = q8((float)acc[mg][ng][0] * cb_lo);
            int q1 = q8((float)acc[mg][ng][1] * cb_lo);
            int q2 = q8((float)acc[mg][ng][2] * cb_hi);
            int q3 = q8((float)acc[mg][ng][3] * cb_hi);
            *(short*)&smem.e[r_lo * ESTRIDE + c] =
                (short)((q0 & 0xFF) | ((q1 & 0xFF) << 8));
            *(short*)&smem.e[(r_lo + 8) * ESTRIDE + c] =
                (short)((q2 & 0xFF) | ((q3 & 0xFF) << 8));
        }
    }
    __syncthreads();

    // Coalesced flush: 128 rows x 128B = 1024 uint4 = 256 threads x 4.
    #pragma unroll
    for (int i = 0; i < 4; i++) {
        int gi = tid + 256 * i;
        int r  = gi >> 3;
        int c  = gi & 7;
        uint4 v = *(const uint4*)&smem.e[r * ESTRIDE + c * 16];
        *(uint4*)(g_q + (size_t)(m0 + r) * NN + n0 + c * 16) = v;
    }
}

// ---------------------------------------------------------------------------
// Kernel 3: per-row finish. One CTA (256 threads) per batch row. Unchanged.
// ---------------------------------------------------------------------------
#define FIN_SMEM ((NN + 64) * 4)   // 33 KB

__device__ __forceinline__ float block_reduce_sum(float v, float* red)
{
    int tid = threadIdx.x;
    #pragma unroll
    for (int o = 16; o; o >>= 1) v += __shfl_xor_sync(0xFFFFFFFFu, v, o);
    if ((tid & 31) == 0) red[tid >> 5] = v;
    __syncthreads();
    if (tid < 32) {
        float x = (tid < 8) ? red[tid] : 0.0f;
        #pragma unroll
        for (int o = 4; o; o >>= 1) x += __shfl_xor_sync(0xFFFFFFFFu, x, o);
        if (tid == 0) red[16] = x;
    }
    __syncthreads();
    return red[16];
}

__global__ __launch_bounds__(256) void finish_kernel(
    const float* __restrict__ prev,
    const float* __restrict__ g,
    const float* __restrict__ s,
    const float* __restrict__ gamma,
    float* __restrict__ out)
{
    extern __shared__ float sm[];
    float* buf = sm;
    float* red = sm + NN;

    int b   = blockIdx.x;
    int tid = threadIdx.x;

    const uint4* q4 = (const uint4*)(g_q + (size_t)b * NN);
    float z = 0.0f;
    #pragma unroll
    for (int j = 0; j < 2; j++) {
        int i = tid + 256 * j;
        uint4 v = q4[i];
        float* dst = &buf[i * 16];
        uint32_t wds[4] = {v.x, v.y, v.z, v.w};
        #pragma unroll
        for (int w = 0; w < 4; w++) {
            uint32_t u = wds[w];
            float e0 = __expf((float)(int)(char)(u)        * QINV);
            float e1 = __expf((float)(int)(char)(u >> 8)   * QINV);
            float e2 = __expf((float)(int)(char)(u >> 16)  * QINV);
            float e3 = __expf((float)(int)(char)(u >> 24)  * QINV);
            dst[4 * w + 0] = e0;
            dst[4 * w + 1] = e1;
            dst[4 * w + 2] = e2;
            dst[4 * w + 3] = e3;
            z += (e0 + e1) + (e2 + e3);
        }
    }
    float Z = block_reduce_sum(z, red);

    float gb = g[b];
    float gm = gamma[b];
    float s0 = s[3 * b], s1 = s[3 * b + 1], s2 = s[3 * b + 2];
    float mx  = fmaxf(s0, fmaxf(s1, s2));
    float es0 = __expf(s0 - mx), es1 = __expf(s1 - mx), es2 = __expf(s2 - mx);
    float inv3 = 1.0f / (es0 + es1 + es2);
    float ss0 = es0 * inv3, ss1 = es1 * inv3, ss2 = es2 * inv3;

    float gcw = gb / Z;
    float om  = 1.0f - gb;

    const float4* p4 = (const float4*)(prev + (size_t)b * NN);
    #pragma unroll
    for (int j = 0; j < 8; j++) {
        int i = tid + 256 * j;
        float4 v = *(float4*)&buf[4 * i];
        float4 p = p4[i];
        v.x = gcw * v.x + om * p.x;
        v.y = gcw * v.y + om * p.y;
        v.z = gcw * v.z + om * p.z;
        v.w = gcw * v.w + om * p.w;
        *(float4*)&buf[4 * i] = v;
    }
    __syncthreads();

    float r[32];
    float ssum = 0.0f;
    #pragma unroll
    for (int j = 0; j < 32; j++) {
        int i = tid + 256 * j;
        float left  = (i > 0)      ? buf[i - 1] : 0.0f;
        float mid   = buf[i];
        float right = (i < NN - 1) ? buf[i + 1] : 0.0f;
        float sh = ss0 * left + ss1 * mid + ss2 * right;
        float sp = __powf(sh, gm);
        r[j] = sp;
        ssum += sp;
    }
    float S  = block_reduce_sum(ssum, red);
    float sc = 1.0f / (S + 1e-8f);

    float* orow = out + (size_t)b * NN;
    #pragma unroll
    for (int j = 0; j < 32; j++)
        orow[tid + 256 * j] = r[j] * sc;
}

// ---------------------------------------------------------------------------
// Launch. Inputs (metadata order): k, beta, g, s, gamma, prev_weights, memory
// Serial single-stream (both overlap schemes measured slower).
// ---------------------------------------------------------------------------
extern "C" void kernel_launch(void* const* d_in, const int* in_sizes, int n_in,
                              void* d_out, int out_size)
{
    const float* K    = (const float*)d_in[0];
    const float* beta = (const float*)d_in[1];
    const float* g    = (const float*)d_in[2];
    const float* s    = (const float*)d_in[3];
    const float* gam  = (const float*)d_in[4];
    const float* prev = (const float*)d_in[5];
    const float* M    = (const float*)d_in[6];
    float* out = (float*)d_out;

    prep_kernel<<<(BB + NN) / 8, 256>>>(K, beta, M);

    // 64 N-tiles x 32 M-tiles (CTA tile 128x128), 256 threads.
    gemm_q_kernel<<<dim3(NN / 128, BB / 128), 256>>>();

    finish_kernel<<<BB, 256, FIN_SMEM>>>(prev, g, s, gam, out);
}

// round 13
// speedup vs baseline: 1.9834x; 1.0609x over previous
#include <cuda_runtime.h>
#include <cuda_fp16.h>
#include <cuda_bf16.h>
#include <cstdint>
#include <cstddef>

// Problem shape (fixed by the dataset)
#define BB 4096   // batch rows
#define NN 8192   // memory slots
#define WW 64     // key width

#define QSCALE 124.0f
#define QINV   (1.0f / 124.0f)
// int8 input quantization: unit vectors scaled by 127; dot scale 1/127^2.
#define CBFAC  (QSCALE / 16129.0f)

// ---------------------------------------------------------------------------
// Scratch (device globals — no allocations allowed)
// g_kb / g_mb hold the int8 operands in MMA *fragment-major* layout:
//   A block (16 rows x 32 kB) -> 512 B: lane-major, 16 B per lane =
//     regs a0..a3; a[r] of lane l = row (l>>2)+8*(r&1),
//     k-bytes 4*(l&3)+16*(r>>1) .. +3.
//   B block (8 cols x 32 kB)  -> 256 B: lane-major, 8 B per lane =
//     regs b0..b1; b[r] of lane l = col (l>>2), k-bytes 4*(l&3)+16*r .. +3.
// So the GEMM fetches fragments with coalesced LDG.128 / LDG.64 directly —
// no SMEM staging, no barriers, no ldmatrix (rounds 11-12 proved the GEMM
// is bound by that serialized chain, not by instructions or occupancy).
// ---------------------------------------------------------------------------
__device__ char  g_kb[(size_t)BB * WW];   // A, fragment-major (256 KB)
__device__ char  g_mb[(size_t)NN * WW];   // B, fragment-major (512 KB)
__device__ float g_cb[BB];                // beta[row] * QSCALE / 127^2
__device__ char  g_q[(size_t)BB * NN];    // int8 quantized beta*sim (32 MB)

__device__ __forceinline__ int q8(float x) {
    return __float2int_rn(fminf(fmaxf(x, -127.0f), 127.0f));
}

// ---------------------------------------------------------------------------
// Kernel 1: normalize rows, quantize to int8 (scale 127), store fragment-major.
// One warp per row; lane L handles k-bytes (2L, 2L+1) — both land in the same
// 4-byte fragment group (2L mod 4 in {0,2}), so one short store suffices.
// ---------------------------------------------------------------------------
__global__ void prep_kernel(const float* __restrict__ K,
                            const float* __restrict__ beta,
                            const float* __restrict__ M)
{
    int w    = (blockIdx.x * blockDim.x + threadIdx.x) >> 5;
    int lane = threadIdx.x & 31;
    if (w >= BB + NN) return;

    bool is_k = (w < BB);
    int  row  = is_k ? w : (w - BB);
    const float* src = (is_k ? K : M) + (size_t)row * WW;

    float x0 = src[2 * lane];
    float x1 = src[2 * lane + 1];
    float ss = x0 * x0 + x1 * x1;
    #pragma unroll
    for (int o = 16; o; o >>= 1) ss += __shfl_xor_sync(0xFFFFFFFFu, ss, o);

    float nrm = sqrtf(ss);
    float sc;
    if (is_k) {
        float a  = 1.0f / fmaxf(nrm, 1e-12f);
        float n2 = nrm * a;                    // ||k_n||
        float b2 = 1.0f / fmaxf(n2, 1e-8f);
        sc = a * b2;                           // unit-vector scale (beta -> g_cb)
        if (lane == 0) g_cb[row] = beta[row] * CBFAC;
    } else {
        sc = 1.0f / fmaxf(nrm, 1e-8f);
    }

    int qa = q8(x0 * sc * 127.0f);
    int qb = q8(x1 * sc * 127.0f);
    short pak = (short)((qa & 0xFF) | ((qb & 0xFF) << 8));

    int kb     = 2 * lane;          // first k-byte this thread owns
    int kblock = kb >> 5;           // 0..1  (two k32 blocks)
    int kk     = kb & 31;

    if (is_k) {
        // A: [mtile(r>>7)] [bm = (r&127)>>4, kblock] [flane] [16B]
        int rloc  = row & 127;
        int bm    = rloc >> 4;
        int rr    = rloc & 15;
        int flane = (rr & 7) * 4 + ((kk & 15) >> 2);
        int reg   = (rr >> 3) + ((kk >> 4) << 1);
        size_t addr = ((size_t)(row >> 7) << 13)
                    + (size_t)(((bm << 1) + kblock) << 9)
                    + flane * 16 + reg * 4 + (kk & 3);
        *(short*)(g_kb + addr) = pak;
    } else {
        // B: [ntile(n>>7)] [bn = (n&127)>>3, kblock] [flane] [8B]
        int nloc  = row & 127;
        int bn    = nloc >> 3;
        int rr    = nloc & 7;
        int flane = rr * 4 + ((kk & 15) >> 2);
        int reg   = kk >> 4;
        size_t addr = ((size_t)(row >> 7) << 13)
                    + (size_t)(((bn << 1) + kblock) << 8)
                    + flane * 8 + reg * 4 + (kk & 3);
        *(short*)(g_mb + addr) = pak;
    }
}

// ---------------------------------------------------------------------------
// Kernel 2: int8 GEMM (mma.sync m16n8k32.s8), fragments loaded directly from
// global (coalesced, L2-resident operands), int8 epilogue via SMEM staging.
// CTA tile 128x128, 8 warps 2(M)x4(N), warp tile 64x32, K=64 (2 k-steps).
// ---------------------------------------------------------------------------
#define ESTRIDE 144   // bytes per staged row (16B-aligned; 36 words, mod32=4)

__global__ __launch_bounds__(256) void gemm_q_kernel()
{
    __shared__ __align__(16) char smem_e[128 * ESTRIDE];
    int tid  = threadIdx.x;
    int wid  = tid >> 5;
    int lane = tid & 31;
    int n0   = blockIdx.x << 7;
    int m0   = blockIdx.y << 7;

    int warp_m = wid >> 2;           // 0..1 -> 64 rows
    int warp_n = wid & 3;            // 0..3 -> 32 cols
    int m_base = warp_m * 64;
    int n_base = warp_n * 32;

    // --- Load all fragments (16 independent coalesced loads, one exposure).
    const char* Abase = g_kb + ((size_t)blockIdx.y << 13);
    const char* Bbase = g_mb + ((size_t)blockIdx.x << 13);

    uint4 afr[4][2];   // [mg][ks] -> regs a0..a3
    #pragma unroll
    for (int mg = 0; mg < 4; mg++)
        #pragma unroll
        for (int ks = 0; ks < 2; ks++) {
            int mb = warp_m * 4 + mg;
            afr[mg][ks] = *(const uint4*)(Abase + (((mb << 1) + ks) << 9) + lane * 16);
        }
    uint2 bfr[4][2];   // [ng][ks] -> regs b0..b1
    #pragma unroll
    for (int ng = 0; ng < 4; ng++)
        #pragma unroll
        for (int ks = 0; ks < 2; ks++) {
            int bn = warp_n * 4 + ng;
            bfr[ng][ks] = *(const uint2*)(Bbase + (((bn << 1) + ks) << 8) + lane * 8);
        }

    int acc[4][4][4];                // [mg][ng][frag], s32
    #pragma unroll
    for (int a = 0; a < 4; a++)
        #pragma unroll
        for (int b = 0; b < 4; b++)
            #pragma unroll
            for (int c = 0; c < 4; c++) acc[a][b][c] = 0;

    #pragma unroll
    for (int ks = 0; ks < 2; ks++)
        #pragma unroll
        for (int mg = 0; mg < 4; mg++)
            #pragma unroll
            for (int ng = 0; ng < 4; ng++) {
                asm volatile(
                    "mma.sync.aligned.m16n8k32.row.col.s32.s8.s8.s32 "
                    "{%0,%1,%2,%3}, {%4,%5,%6,%7}, {%8,%9}, {%0,%1,%2,%3};"
                    : "+r"(acc[mg][ng][0]), "+r"(acc[mg][ng][1]),
                      "+r"(acc[mg][ng][2]), "+r"(acc[mg][ng][3])
                    : "r"(afr[mg][ks].x), "r"(afr[mg][ks].y),
                      "r"(afr[mg][ks].z), "r"(afr[mg][ks].w),
                      "r"(bfr[ng][ks].x), "r"(bfr[ng][ks].y));
            }

    // --- Epilogue: scale by per-row cb, quantize, stage, coalesced flush.
    int groupr = lane >> 2;
    int cpair  = (lane & 3) << 1;
    #pragma unroll
    for (int mg = 0; mg < 4; mg++) {
        int r_lo = m_base + mg * 16 + groupr;
        float cb_lo = g_cb[m0 + r_lo];
        float cb_hi = g_cb[m0 + r_lo + 8];
        #pragma unroll
        for (int ng = 0; ng < 4; ng++) {
            int c = n_base + ng * 8 + cpair;
            int q0 = q8((float)acc[mg][ng][0] * cb_lo);
            int q1 = q8((float)acc[mg][ng][1] * cb_lo);
            int q2 = q8((float)acc[mg][ng][2] * cb_hi);
            int q3 = q8((float)acc[mg][ng][3] * cb_hi);
            *(short*)&smem_e[r_lo * ESTRIDE + c] =
                (short)((q0 & 0xFF) | ((q1 & 0xFF) << 8));
            *(short*)&smem_e[(r_lo + 8) * ESTRIDE + c] =
                (short)((q2 & 0xFF) | ((q3 & 0xFF) << 8));
        }
    }
    __syncthreads();

    // Coalesced flush: 128 rows x 128B = 1024 uint4 = 256 threads x 4.
    #pragma unroll
    for (int i = 0; i < 4; i++) {
        int gi = tid + 256 * i;
        int r  = gi >> 3;
        int c  = gi & 7;
        uint4 v = *(const uint4*)&smem_e[r * ESTRIDE + c * 16];
        *(uint4*)(g_q + (size_t)(m0 + r) * NN + n0 + c * 16) = v;
    }
}

// ---------------------------------------------------------------------------
// Kernel 3: per-row finish. One CTA (256 threads) per batch row. Unchanged.
// ---------------------------------------------------------------------------
#define FIN_SMEM ((NN + 64) * 4)   // 33 KB

__device__ __forceinline__ float block_reduce_sum(float v, float* red)
{
    int tid = threadIdx.x;
    #pragma unroll
    for (int o = 16; o; o >>= 1) v += __shfl_xor_sync(0xFFFFFFFFu, v, o);
    if ((tid & 31) == 0) red[tid >> 5] = v;
    __syncthreads();
    if (tid < 32) {
        float x = (tid < 8) ? red[tid] : 0.0f;
        #pragma unroll
        for (int o = 4; o; o >>= 1) x += __shfl_xor_sync(0xFFFFFFFFu, x, o);
        if (tid == 0) red[16] = x;
    }
    __syncthreads();
    return red[16];
}

__global__ __launch_bounds__(256) void finish_kernel(
    const float* __restrict__ prev,
    const float* __restrict__ g,
    const float* __restrict__ s,
    const float* __restrict__ gamma,
    float* __restrict__ out)
{
    extern __shared__ float sm[];
    float* buf = sm;
    float* red = sm + NN;

    int b   = blockIdx.x;
    int tid = threadIdx.x;

    const uint4* q4 = (const uint4*)(g_q + (size_t)b * NN);
    float z = 0.0f;
    #pragma unroll
    for (int j = 0; j < 2; j++) {
        int i = tid + 256 * j;
        uint4 v = q4[i];
        float* dst = &buf[i * 16];
        uint32_t wds[4] = {v.x, v.y, v.z, v.w};
        #pragma unroll
        for (int w = 0; w < 4; w++) {
            uint32_t u = wds[w];
            float e0 = __expf((float)(int)(char)(u)        * QINV);
            float e1 = __expf((float)(int)(char)(u >> 8)   * QINV);
            float e2 = __expf((float)(int)(char)(u >> 16)  * QINV);
            float e3 = __expf((float)(int)(char)(u >> 24)  * QINV);
            dst[4 * w + 0] = e0;
            dst[4 * w + 1] = e1;
            dst[4 * w + 2] = e2;
            dst[4 * w + 3] = e3;
            z += (e0 + e1) + (e2 + e3);
        }
    }
    float Z = block_reduce_sum(z, red);

    float gb = g[b];
    float gm = gamma[b];
    float s0 = s[3 * b], s1 = s[3 * b + 1], s2 = s[3 * b + 2];
    float mx  = fmaxf(s0, fmaxf(s1, s2));
    float es0 = __expf(s0 - mx), es1 = __expf(s1 - mx), es2 = __expf(s2 - mx);
    float inv3 = 1.0f / (es0 + es1 + es2);
    float ss0 = es0 * inv3, ss1 = es1 * inv3, ss2 = es2 * inv3;

    float gcw = gb / Z;
    float om  = 1.0f - gb;

    const float4* p4 = (const float4*)(prev + (size_t)b * NN);
    #pragma unroll
    for (int j = 0; j < 8; j++) {
        int i = tid + 256 * j;
        float4 v = *(float4*)&buf[4 * i];
        float4 p = p4[i];
        v.x = gcw * v.x + om * p.x;
        v.y = gcw * v.y + om * p.y;
        v.z = gcw * v.z + om * p.z;
        v.w = gcw * v.w + om * p.w;
        *(float4*)&buf[4 * i] = v;
    }
    __syncthreads();

    float r[32];
    float ssum = 0.0f;
    #pragma unroll
    for (int j = 0; j < 32; j++) {
        int i = tid + 256 * j;
        float left  = (i > 0)      ? buf[i - 1] : 0.0f;
        float mid   = buf[i];
        float right = (i < NN - 1) ? buf[i + 1] : 0.0f;
        float sh = ss0 * left + ss1 * mid + ss2 * right;
        float sp = __powf(sh, gm);
        r[j] = sp;
        ssum += sp;
    }
    float S  = block_reduce_sum(ssum, red);
    float sc = 1.0f / (S + 1e-8f);

    float* orow = out + (size_t)b * NN;
    #pragma unroll
    for (int j = 0; j < 32; j++)
        orow[tid + 256 * j] = r[j] * sc;
}

// ---------------------------------------------------------------------------
// Launch. Inputs (metadata order): k, beta, g, s, gamma, prev_weights, memory
// Serial single-stream (both overlap schemes measured slower).
// ---------------------------------------------------------------------------
extern "C" void kernel_launch(void* const* d_in, const int* in_sizes, int n_in,
                              void* d_out, int out_size)
{
    const float* K    = (const float*)d_in[0];
    const float* beta = (const float*)d_in[1];
    const float* g    = (const float*)d_in[2];
    const float* s    = (const float*)d_in[3];
    const float* gam  = (const float*)d_in[4];
    const float* prev = (const float*)d_in[5];
    const float* M    = (const float*)d_in[6];
    float* out = (float*)d_out;

    prep_kernel<<<(BB + NN) / 8, 256>>>(K, beta, M);

    // 64 N-tiles x 32 M-tiles (CTA tile 128x128), 256 threads.
    gemm_q_kernel<<<dim3(NN / 128, BB / 128), 256>>>();

    finish_kernel<<<BB, 256, FIN_SMEM>>>(prev, g, s, gam, out);
}